// round 2
// baseline (speedup 1.0000x reference)
#include <cuda_runtime.h>

#define HDIM 1024
#define LSEQ 512
#define G4   4096      // 4*H gate rows
#define KIN  4096      // input feature dim (2H + 2H)
#define NLAB 122
#define RGRID 128      // recurrent kernel CTAs (<=148 so one wave, persistent-safe)

// ---------------- scratch (no allocation allowed; device globals) -------------
__device__ float    g_Wcomb[G4 * HDIM];   // W_ih[:,4096:] + W_hh   (16.8 MB)
__device__ float    g_bias[G4];           // b_ih + b_hh
__device__ float    g_Xpre[LSEQ * G4];    // input projection + bias (8.4 MB)
__device__ float    g_outs[LSEQ * HDIM];  // h_t for all steps       (2.1 MB)
__device__ unsigned g_ctr;                // grid barrier counter

// ---------------- prep: fold recurrent weights & biases, reset barrier --------
__global__ void prep_kernel(const float* __restrict__ W_ih,
                            const float* __restrict__ W_hh,
                            const float* __restrict__ b_ih,
                            const float* __restrict__ b_hh) {
    int idx = blockIdx.x * blockDim.x + threadIdx.x;
    if (idx < G4 * HDIM) {
        int r = idx >> 10;           // row (gate index)
        int c = idx & 1023;          // col (h index)
        g_Wcomb[idx] = W_ih[(size_t)r * 5120 + 4096 + c] + W_hh[idx];
    }
    if (idx < G4) g_bias[idx] = b_ih[idx] + b_hh[idx];
    if (idx == 0) g_ctr = 0u;
}

// ---------------- pregemm: Xpre[t][r] = bias[r] + sum_k W_ih[r][k]*feats[t][k]
// feats[t][k] = k<2048 ? x[t][k] : hi[t][k-2048]
#define BM 128
#define BN 128
#define BK 16
#define TM 8
#define TN 8

__global__ __launch_bounds__(256) void pregemm_kernel(
    const float* __restrict__ x, const float* __restrict__ hi,
    const float* __restrict__ W_ih) {
    __shared__ float As[BK][BM + 4];   // [k][m]  (m = timestep)
    __shared__ float Bs[BK][BN + 4];   // [k][n]  (n = gate row)

    const int bm = blockIdx.x * BM;
    const int bn = blockIdx.y * BN;
    const int tid = threadIdx.x;
    const int tr = tid / 16;           // 0..15
    const int tc = tid % 16;           // 0..15

    float acc[TM][TN];
#pragma unroll
    for (int i = 0; i < TM; i++)
#pragma unroll
        for (int j = 0; j < TN; j++) acc[i][j] = 0.f;

    for (int k0 = 0; k0 < KIN; k0 += BK) {
        // load A tile (feats)
#pragma unroll
        for (int i = tid; i < BM * BK; i += 256) {
            int m = i / BK, k = i % BK;
            int gk = k0 + k;
            float v = (gk < 2048) ? x[(size_t)(bm + m) * 2048 + gk]
                                  : hi[(size_t)(bm + m) * 2048 + gk - 2048];
            As[k][m] = v;
        }
        // load B tile (W_ih, row stride 5120, first 4096 cols)
#pragma unroll
        for (int i = tid; i < BN * BK; i += 256) {
            int n = i / BK, k = i % BK;
            Bs[k][n] = W_ih[(size_t)(bn + n) * 5120 + k0 + k];
        }
        __syncthreads();
#pragma unroll
        for (int k = 0; k < BK; k++) {
            float a[TM], b[TN];
#pragma unroll
            for (int i = 0; i < TM; i++) a[i] = As[k][tr * TM + i];
#pragma unroll
            for (int j = 0; j < TN; j++) b[j] = Bs[k][tc * TN + j];
#pragma unroll
            for (int i = 0; i < TM; i++)
#pragma unroll
                for (int j = 0; j < TN; j++) acc[i][j] += a[i] * b[j];
        }
        __syncthreads();
    }
#pragma unroll
    for (int i = 0; i < TM; i++) {
        int m = bm + tr * TM + i;
#pragma unroll
        for (int j = 0; j < TN; j++) {
            int n = bn + tc * TN + j;
            g_Xpre[(size_t)m * G4 + n] = acc[i][j] + g_bias[n];
        }
    }
}

// ---------------- recurrent persistent kernel --------------------------------
__device__ __forceinline__ float fast_sigmoid(float v) {
    return 1.f / (1.f + __expf(-v));
}
__device__ __forceinline__ float fast_tanh(float v) {
    v = fminf(fmaxf(v, -15.f), 15.f);
    float e = __expf(-2.f * v);
    return (1.f - e) / (1.f + e);
}

__global__ __launch_bounds__(256, 1) void recur_kernel() {
    __shared__ float h_s[HDIM];
    const int tid  = threadIdx.x;
    const int lane = tid & 31;
    const int warp = tid >> 5;                 // 0..7
    const int j    = blockIdx.x * 8 + warp;    // h element, 0..1023

    // Load this warp's 4 gate rows of W_comb into registers.
    // col layout: lane handles cols {lane, lane+32, ..., lane+992}
    float w[4][32];
#pragma unroll
    for (int g = 0; g < 4; g++) {
        const float* base = g_Wcomb + (size_t)(j + g * HDIM) * HDIM;
#pragma unroll
        for (int k = 0; k < 32; k++) w[g][k] = base[k * 32 + lane];
    }

    float c_state = 0.f;    // meaningful on lane 0 only

    for (int t = 0; t < LSEQ; t++) {
        // stage h_{t-1} into shared (h_{-1} = 0)
        if (t == 0) {
            for (int i = tid; i < HDIM; i += 256) h_s[i] = 0.f;
        } else {
            const float* hp = g_outs + (size_t)(t - 1) * HDIM;
            for (int i = tid; i < HDIM; i += 256) h_s[i] = hp[i];
        }
        __syncthreads();

        float a0 = 0.f, a1 = 0.f, a2 = 0.f, a3 = 0.f;
#pragma unroll
        for (int k = 0; k < 32; k++) {
            float hv = h_s[k * 32 + lane];
            a0 += w[0][k] * hv;
            a1 += w[1][k] * hv;
            a2 += w[2][k] * hv;
            a3 += w[3][k] * hv;
        }
#pragma unroll
        for (int off = 16; off > 0; off >>= 1) {
            a0 += __shfl_down_sync(0xffffffffu, a0, off);
            a1 += __shfl_down_sync(0xffffffffu, a1, off);
            a2 += __shfl_down_sync(0xffffffffu, a2, off);
            a3 += __shfl_down_sync(0xffffffffu, a3, off);
        }
        if (lane == 0) {
            const float* xp = g_Xpre + (size_t)t * G4;
            float gi = xp[j]        + a0;
            float gf = xp[j + 1024] + a1;
            float gg = xp[j + 2048] + a2;
            float go = xp[j + 3072] + a3;
            float si = fast_sigmoid(gi);
            float sf = fast_sigmoid(gf);
            float so = fast_sigmoid(go);
            c_state = sf * c_state + si * fast_tanh(gg);
            g_outs[(size_t)t * HDIM + j] = so * fast_tanh(c_state);
        }
        __threadfence();        // order h store before barrier arrival
        __syncthreads();        // also protects h_s reuse next iteration

        // grid-wide barrier (monotonic counter; reset by prep each launch)
        if (tid == 0) {
            atomicAdd(&g_ctr, 1u);
            unsigned target = (unsigned)RGRID * (unsigned)(t + 1);
            while (atomicAdd(&g_ctr, 0u) < target) { }
        }
        __syncthreads();
    }
}

// ---------------- final FC: out[t][l] = b_fc[l] + outs[t] . W_fc[l] ----------
__global__ __launch_bounds__(128) void fc_kernel(const float* __restrict__ W_fc,
                                                 const float* __restrict__ b_fc,
                                                 float* __restrict__ out) {
    __shared__ float hrow[HDIM];
    const int t = blockIdx.x;
    const int tid = threadIdx.x;
    for (int i = tid; i < HDIM; i += 128) hrow[i] = g_outs[(size_t)t * HDIM + i];
    __syncthreads();
    if (tid < NLAB) {
        const float* wr = W_fc + (size_t)tid * HDIM;
        float s0 = 0.f, s1 = 0.f, s2 = 0.f, s3 = 0.f;
#pragma unroll 4
        for (int k = 0; k < HDIM; k += 4) {
            s0 += wr[k]     * hrow[k];
            s1 += wr[k + 1] * hrow[k + 1];
            s2 += wr[k + 2] * hrow[k + 2];
            s3 += wr[k + 3] * hrow[k + 3];
        }
        out[(size_t)t * NLAB + tid] = s0 + s1 + s2 + s3 + b_fc[tid];
    }
}

// ---------------- launch ------------------------------------------------------
extern "C" void kernel_launch(void* const* d_in, const int* in_sizes, int n_in,
                              void* d_out, int out_size) {
    const float* x    = (const float*)d_in[0];
    const float* hi   = (const float*)d_in[1];
    const float* W_ih = (const float*)d_in[2];
    const float* W_hh = (const float*)d_in[3];
    const float* b_ih = (const float*)d_in[4];
    const float* b_hh = (const float*)d_in[5];
    const float* W_fc = (const float*)d_in[6];
    const float* b_fc = (const float*)d_in[7];
    float* out = (float*)d_out;

    prep_kernel<<<(G4 * HDIM + 255) / 256, 256>>>(W_ih, W_hh, b_ih, b_hh);

    dim3 pgrid(LSEQ / BM, G4 / BN);   // (4, 32)
    pregemm_kernel<<<pgrid, 256>>>(x, hi, W_ih);

    recur_kernel<<<RGRID, 256>>>();

    fc_kernel<<<LSEQ, 128>>>(W_fc, b_fc, out);
}

// round 3
// speedup vs baseline: 1.5615x; 1.5615x over previous
#include <cuda_runtime.h>

#define HDIM 1024
#define LSEQ 512
#define G4   4096      // 4*H gate rows
#define KIN  4096      // input feature dim (2H + 2H)
#define NLAB 122
#define RGRID 128      // recurrent kernel CTAs (<=148: one wave, persistent-safe)

// ---------------- scratch (no allocation allowed; device globals) -------------
__device__ __align__(256) float g_Wcomb[G4 * HDIM];   // W_ih[:,4096:] + W_hh
__device__ __align__(256) float g_bias[G4];           // b_ih + b_hh
__device__ __align__(256) float g_Xpre[LSEQ * G4];    // input projection + bias
__device__ __align__(256) float g_outs[LSEQ * HDIM];  // h_t for all steps
__device__ unsigned g_ctr;                            // grid barrier counter

// ---------------- prep: fold recurrent weights & biases, reset barrier --------
__global__ void prep_kernel(const float* __restrict__ W_ih,
                            const float* __restrict__ W_hh,
                            const float* __restrict__ b_ih,
                            const float* __restrict__ b_hh) {
    int idx = blockIdx.x * blockDim.x + threadIdx.x;
    if (idx < G4 * HDIM) {
        int r = idx >> 10;           // gate row
        int c = idx & 1023;          // h col
        g_Wcomb[idx] = W_ih[(size_t)r * 5120 + 4096 + c] + W_hh[idx];
    }
    if (idx < G4) g_bias[idx] = b_ih[idx] + b_hh[idx];
    if (idx == 0) g_ctr = 0u;
}

// ---------------- pregemm: Xpre[t][r] = bias[r] + W_ih[r, :4096] . feats[t] ---
#define BM 128
#define BN 128
#define BK 16
#define TM 8
#define TN 8

__global__ __launch_bounds__(256) void pregemm_kernel(
    const float* __restrict__ x, const float* __restrict__ hi,
    const float* __restrict__ W_ih) {
    __shared__ float As[BK][BM + 4];   // [k][m]  (m = timestep)
    __shared__ float Bs[BK][BN + 4];   // [k][n]  (n = gate row)

    const int bm = blockIdx.x * BM;
    const int bn = blockIdx.y * BN;
    const int tid = threadIdx.x;
    const int tr = tid / 16;
    const int tc = tid % 16;

    float acc[TM][TN];
#pragma unroll
    for (int i = 0; i < TM; i++)
#pragma unroll
        for (int j = 0; j < TN; j++) acc[i][j] = 0.f;

    for (int k0 = 0; k0 < KIN; k0 += BK) {
        // A tile: 128 rows x 16 floats = 512 float4, 256 threads -> 2 each.
        // A float4 never straddles the x/hi boundary (2048 is a multiple of 16).
#pragma unroll
        for (int it = 0; it < 2; it++) {
            int idx = tid + it * 256;           // 0..511
            int m = idx >> 2;
            int kq = idx & 3;                    // which float4 within the 16
            int gk = k0 + kq * 4;
            float4 v;
            if (gk < 2048)
                v = *(const float4*)(x + (size_t)(bm + m) * 2048 + gk);
            else
                v = *(const float4*)(hi + (size_t)(bm + m) * 2048 + gk - 2048);
            As[kq * 4 + 0][m] = v.x;
            As[kq * 4 + 1][m] = v.y;
            As[kq * 4 + 2][m] = v.z;
            As[kq * 4 + 3][m] = v.w;
        }
        // B tile: W_ih rows are 5120 floats (20480B, 16B-aligned)
#pragma unroll
        for (int it = 0; it < 2; it++) {
            int idx = tid + it * 256;
            int n = idx >> 2;
            int kq = idx & 3;
            float4 v = *(const float4*)(W_ih + (size_t)(bn + n) * 5120 + k0 + kq * 4);
            Bs[kq * 4 + 0][n] = v.x;
            Bs[kq * 4 + 1][n] = v.y;
            Bs[kq * 4 + 2][n] = v.z;
            Bs[kq * 4 + 3][n] = v.w;
        }
        __syncthreads();
#pragma unroll
        for (int k = 0; k < BK; k++) {
            float a[TM], b[TN];
#pragma unroll
            for (int i = 0; i < TM; i++) a[i] = As[k][tr * TM + i];
#pragma unroll
            for (int j = 0; j < TN; j++) b[j] = Bs[k][tc * TN + j];
#pragma unroll
            for (int i = 0; i < TM; i++)
#pragma unroll
                for (int j = 0; j < TN; j++) acc[i][j] += a[i] * b[j];
        }
        __syncthreads();
    }
#pragma unroll
    for (int i = 0; i < TM; i++) {
        int m = bm + tr * TM + i;
#pragma unroll
        for (int j = 0; j < TN; j++) {
            int n = bn + tc * TN + j;
            g_Xpre[(size_t)m * G4 + n] = acc[i][j] + g_bias[n];
        }
    }
}

// ---------------- recurrent persistent kernel --------------------------------
__device__ __forceinline__ float fast_sigmoid(float v) {
    return 1.f / (1.f + __expf(-v));
}
__device__ __forceinline__ float fast_tanh(float v) {
    v = fminf(fmaxf(v, -15.f), 15.f);
    float e = __expf(-2.f * v);
    return (1.f - e) / (1.f + e);
}

__global__ __launch_bounds__(256, 1) void recur_kernel() {
    __shared__ float h_s[HDIM];
    const int tid  = threadIdx.x;
    const int lane = tid & 31;
    const int warp = tid >> 5;                 // 0..7
    const int j    = blockIdx.x * 8 + warp;    // h element, 0..1023

    // This warp's 4 gate rows of W_comb live in registers.
    // Lane handles cols {lane, lane+32, ..., lane+992}.
    float w[4][32];
#pragma unroll
    for (int g = 0; g < 4; g++) {
        const float* base = g_Wcomb + (size_t)(j + g * HDIM) * HDIM;
#pragma unroll
        for (int k = 0; k < 32; k++) w[g][k] = base[k * 32 + lane];
    }

    float c_state = 0.f;    // meaningful on lane 0 only

    for (int t = 0; t < LSEQ; t++) {
        // Prefetch the precomputed gate terms (off the h critical path)
        float xi = 0.f, xf = 0.f, xg = 0.f, xo = 0.f;
        if (lane == 0) {
            const float* xp = g_Xpre + (size_t)t * G4;
            xi = __ldg(xp + j);
            xf = __ldg(xp + j + 1024);
            xg = __ldg(xp + j + 2048);
            xo = __ldg(xp + j + 3072);
        }

        // Stage h_{t-1} into shared (h_{-1} = 0). Bypass L1 for cross-CTA data.
        if (t == 0) {
            ((float4*)h_s)[tid] = make_float4(0.f, 0.f, 0.f, 0.f);
        } else {
            const float4* hp4 = (const float4*)(g_outs + (size_t)(t - 1) * HDIM);
            ((float4*)h_s)[tid] = __ldcg(hp4 + tid);
        }
        __syncthreads();

        float a0 = 0.f, a1 = 0.f, a2 = 0.f, a3 = 0.f;
#pragma unroll
        for (int k = 0; k < 32; k++) {
            float hv = h_s[k * 32 + lane];
            a0 += w[0][k] * hv;
            a1 += w[1][k] * hv;
            a2 += w[2][k] * hv;
            a3 += w[3][k] * hv;
        }
#pragma unroll
        for (int off = 16; off > 0; off >>= 1) {
            a0 += __shfl_down_sync(0xffffffffu, a0, off);
            a1 += __shfl_down_sync(0xffffffffu, a1, off);
            a2 += __shfl_down_sync(0xffffffffu, a2, off);
            a3 += __shfl_down_sync(0xffffffffu, a3, off);
        }
        if (lane == 0) {
            float gi = xi + a0;
            float gf = xf + a1;
            float gg = xg + a2;
            float go = xo + a3;
            float si = fast_sigmoid(gi);
            float sf = fast_sigmoid(gf);
            float so = fast_sigmoid(go);
            c_state = sf * c_state + si * fast_tanh(gg);
            g_outs[(size_t)t * HDIM + j] = so * fast_tanh(c_state);
            __threadfence();    // writer lanes only: order h store before arrival
        }
        __syncthreads();

        // Grid barrier: one atomic arrival per CTA, plain-load polling
        // (read-only polls don't serialize at the LTS atomic ALU).
        if (t < LSEQ - 1) {
            if (tid == 0) {
                atomicAdd(&g_ctr, 1u);
                unsigned target = (unsigned)RGRID * (unsigned)(t + 1);
                while (*(volatile unsigned*)&g_ctr < target) { }
            }
            __syncthreads();
        }
    }
}

// ---------------- final FC: out[t][l] = b_fc[l] + outs[t] . W_fc[l] ----------
// 4 timesteps per block: weight float4s are loaded once and reused 4x.
__global__ __launch_bounds__(128) void fc_kernel(const float* __restrict__ W_fc,
                                                 const float* __restrict__ b_fc,
                                                 float* __restrict__ out) {
    __shared__ float hs[4][HDIM];
    const int t0  = blockIdx.x * 4;
    const int tid = threadIdx.x;

    const float4* src = (const float4*)(g_outs + (size_t)t0 * HDIM);
    float4* dst = (float4*)hs;
#pragma unroll
    for (int i = tid; i < HDIM; i += 128) dst[i] = src[i];   // 4*1024 floats = 1024 f4
    __syncthreads();

    if (tid < NLAB) {
        const float4* wr = (const float4*)(W_fc + (size_t)tid * HDIM);
        float s0 = 0.f, s1 = 0.f, s2 = 0.f, s3 = 0.f;
        const float4* h0 = (const float4*)hs[0];
        const float4* h1 = (const float4*)hs[1];
        const float4* h2 = (const float4*)hs[2];
        const float4* h3 = (const float4*)hs[3];
#pragma unroll 8
        for (int k = 0; k < HDIM / 4; k++) {
            float4 w = wr[k];
            float4 a = h0[k], b = h1[k], c = h2[k], d = h3[k];
            s0 += w.x * a.x + w.y * a.y + w.z * a.z + w.w * a.w;
            s1 += w.x * b.x + w.y * b.y + w.z * b.z + w.w * b.w;
            s2 += w.x * c.x + w.y * c.y + w.z * c.z + w.w * c.w;
            s3 += w.x * d.x + w.y * d.y + w.z * d.z + w.w * d.w;
        }
        float bb = b_fc[tid];
        out[(size_t)(t0 + 0) * NLAB + tid] = s0 + bb;
        out[(size_t)(t0 + 1) * NLAB + tid] = s1 + bb;
        out[(size_t)(t0 + 2) * NLAB + tid] = s2 + bb;
        out[(size_t)(t0 + 3) * NLAB + tid] = s3 + bb;
    }
}

// ---------------- launch ------------------------------------------------------
extern "C" void kernel_launch(void* const* d_in, const int* in_sizes, int n_in,
                              void* d_out, int out_size) {
    const float* x    = (const float*)d_in[0];
    const float* hi   = (const float*)d_in[1];
    const float* W_ih = (const float*)d_in[2];
    const float* W_hh = (const float*)d_in[3];
    const float* b_ih = (const float*)d_in[4];
    const float* b_hh = (const float*)d_in[5];
    const float* W_fc = (const float*)d_in[6];
    const float* b_fc = (const float*)d_in[7];
    float* out = (float*)d_out;

    prep_kernel<<<(G4 * HDIM + 255) / 256, 256>>>(W_ih, W_hh, b_ih, b_hh);

    dim3 pgrid(LSEQ / BM, G4 / BN);   // (4, 32)
    pregemm_kernel<<<pgrid, 256>>>(x, hi, W_ih);

    recur_kernel<<<RGRID, 256>>>();

    fc_kernel<<<LSEQ / 4, 128>>>(W_fc, b_fc, out);
}